// round 15
// baseline (speedup 1.0000x reference)
#include <cuda_runtime.h>
#include <cuda_bf16.h>
#include <cstdint>
#include <math.h>

// ---------------------------------------------------------------------------
// Shapes (fixed): T=2048, B=16, D=1024.  M = T*B = 32768, K = N = 1024.
//   xw = x @ W_x^T + b  via mma.sync bf16 hi/lo split (3 MMAs), fp32 accum.
//   A and W pre-split fp32 -> bf16 hi/lo; GEMM stages all via cp.async.
//   scan: h_t = tanh(xw_t + d_c * h_{t-1}); out_t = h_t^2 * sigmoid(h_t)
//   d_out = [ output (T*B*D) | h ((T+1)*B*D) ]
// R15: GEMM 2 CTAs/SM (BM=64, BN=128, 256 thr, 48KB/stage x2) so one CTA's
// barrier/cp.async drains are covered by the other. Scan/splits = R14.
// ---------------------------------------------------------------------------

#define KDIM 1024
#define BM 64
#define BN 128
#define BK 64                 // 64 bf16 = 128 B rows -> swizzled
#define NK (KDIM / BK)        // 16

__device__ __align__(128) float         g_xw [2048 * 16 * 1024];  // 128 MB
__device__ __align__(128) __nv_bfloat16 g_Ahi[32768 * 1024];      // 64 MB
__device__ __align__(128) __nv_bfloat16 g_Alo[32768 * 1024];      // 64 MB
__device__ __align__(128) __nv_bfloat16 g_Whi[1024 * 1024];       // 2 MB
__device__ __align__(128) __nv_bfloat16 g_Wlo[1024 * 1024];       // 2 MB

// ---------------------------------------------------------------------------
__device__ __forceinline__ void split4(float4 v, uint2& hi, uint2& lo) {
    __nv_bfloat16 hx = __float2bfloat16(v.x), hy = __float2bfloat16(v.y);
    __nv_bfloat16 hz = __float2bfloat16(v.z), hw = __float2bfloat16(v.w);
    __nv_bfloat16 lx = __float2bfloat16(v.x - __bfloat162float(hx));
    __nv_bfloat16 ly = __float2bfloat16(v.y - __bfloat162float(hy));
    __nv_bfloat16 lz = __float2bfloat16(v.z - __bfloat162float(hz));
    __nv_bfloat16 lw = __float2bfloat16(v.w - __bfloat162float(hw));
    __nv_bfloat162 h01 = __halves2bfloat162(hx, hy), h23 = __halves2bfloat162(hz, hw);
    __nv_bfloat162 l01 = __halves2bfloat162(lx, ly), l23 = __halves2bfloat162(lz, lw);
    hi.x = *reinterpret_cast<uint32_t*>(&h01); hi.y = *reinterpret_cast<uint32_t*>(&h23);
    lo.x = *reinterpret_cast<uint32_t*>(&l01); lo.y = *reinterpret_cast<uint32_t*>(&l23);
}
__global__ void splitA_kernel(const float4* __restrict__ src, int n4) {
    int i = blockIdx.x * blockDim.x + threadIdx.x;
    if (i >= n4) return;
    uint2 hi, lo; split4(src[i], hi, lo);
    reinterpret_cast<uint2*>(g_Ahi)[i] = hi;
    reinterpret_cast<uint2*>(g_Alo)[i] = lo;
}
__global__ void splitW_kernel(const float4* __restrict__ src, int n4) {
    int i = blockIdx.x * blockDim.x + threadIdx.x;
    if (i >= n4) return;
    uint2 hi, lo; split4(src[i], hi, lo);
    reinterpret_cast<uint2*>(g_Whi)[i] = hi;
    reinterpret_cast<uint2*>(g_Wlo)[i] = lo;
}

// ---------------------------------------------------------------------------
__device__ __forceinline__ uint32_t smem_u32(const void* p) {
    uint32_t a;
    asm("{ .reg .u64 t; cvta.to.shared.u64 t, %1; cvt.u32.u64 %0, t; }" : "=r"(a) : "l"(p));
    return a;
}
__device__ __forceinline__ void cp16(uint32_t dst, const void* src) {
    asm volatile("cp.async.cg.shared.global [%0], [%1], 16;" :: "r"(dst), "l"(src));
}
#define CP_COMMIT() asm volatile("cp.async.commit_group;" ::: "memory")
#define CP_WAIT(n)  asm volatile("cp.async.wait_group %0;" :: "n"(n) : "memory")

__device__ __forceinline__ void ldm_x4(uint32_t* r, uint32_t addr) {
    asm volatile("ldmatrix.sync.aligned.m8n8.x4.shared.b16 {%0,%1,%2,%3}, [%4];"
                 : "=r"(r[0]), "=r"(r[1]), "=r"(r[2]), "=r"(r[3]) : "r"(addr));
}
__device__ __forceinline__ void mma16816(float* d, const uint32_t* a,
                                         const uint32_t* b) {
    asm volatile(
        "mma.sync.aligned.m16n8k16.row.col.f32.bf16.bf16.f32 "
        "{%0,%1,%2,%3}, {%4,%5,%6,%7}, {%8,%9}, {%0,%1,%2,%3};"
        : "+f"(d[0]), "+f"(d[1]), "+f"(d[2]), "+f"(d[3])
        : "r"(a[0]), "r"(a[1]), "r"(a[2]), "r"(a[3]), "r"(b[0]), "r"(b[1]));
}

// SMEM per stage: Ahi(8K) Alo(8K) Bhi(16K) Blo(16K) = 48 KB; 2 stages.
#define STG_BYTES   (48 * 1024)
#define OFF_AH      0
#define OFF_AL      (8 * 1024)
#define OFF_BH      (16 * 1024)
#define OFF_BL      (32 * 1024)
#define SMEM_TOTAL  (2 * STG_BYTES)   // 96 KB per CTA -> 2 CTAs/SM

__device__ __forceinline__ uint32_t tswz(int row, int c) {
    return (uint32_t)(row * 128 + ((c ^ (row & 7)) * 16));
}

// ---------------------------------------------------------------------------
// GEMM: g_xw[m,n] = sum_k A[m,k]*W[n,k] + bias[n]
// 256 threads, 8 warps in 2(m) x 4(n); warp tile 32x32 (R8 inner loop).
// 2 CTAs/SM: one CTA computes while the other drains its barrier/cp.async.
// ---------------------------------------------------------------------------
__global__ __launch_bounds__(256, 2)
void gemm_mma_kernel(const float* __restrict__ bias) {
    extern __shared__ char smem[];
    const uint32_t sb = smem_u32(smem);
    const int tid = threadIdx.x;
    const int wid = tid >> 5;
    const int lane = tid & 31;
    const int m0 = blockIdx.y * BM;
    const int n0 = blockIdx.x * BN;

    const int warp_m = wid & 1;    // 0..1 -> 32 rows
    const int warp_n = wid >> 1;   // 0..3 -> 32 cols

    // Loaders (256 thr): A 64 rows, 4 thr/row, 2 chunks; B 128 rows, 2 thr/row, 4 chunks.
    const int arow = tid >> 2;           // 0..63
    const int ac0  = (tid & 3) * 2;
    const int brow = tid >> 1;           // 0..127
    const int bc0  = (tid & 1) * 4;

    auto stage_in = [&](int kt, int stg) {
        const uint32_t base = sb + stg * STG_BYTES;
        const size_t ga = (size_t)(m0 + arow) * KDIM + kt * BK;
        const size_t gb = (size_t)(n0 + brow) * KDIM + kt * BK;
#pragma unroll
        for (int j = 0; j < 2; ++j) {
            const int c = ac0 + j;
            const uint32_t so = tswz(arow, c);
            cp16(base + OFF_AH + so, g_Ahi + ga + c * 8);
            cp16(base + OFF_AL + so, g_Alo + ga + c * 8);
        }
#pragma unroll
        for (int j = 0; j < 4; ++j) {
            const int c = bc0 + j;
            const uint32_t so = tswz(brow, c);
            cp16(base + OFF_BH + so, g_Whi + gb + c * 8);
            cp16(base + OFF_BL + so, g_Wlo + gb + c * 8);
        }
        CP_COMMIT();
    };

    float acc[2][4][4];
#pragma unroll
    for (int i = 0; i < 2; ++i)
#pragma unroll
        for (int j = 0; j < 4; ++j)
#pragma unroll
            for (int q = 0; q < 4; ++q) acc[i][j][q] = 0.0f;

    stage_in(0, 0);

    const int lmat  = lane >> 3;
    const int lrow8 = lane & 7;

    for (int kt = 0; kt < NK; ++kt) {
        CP_WAIT(0);
        __syncthreads();

        if (kt + 1 < NK) stage_in(kt + 1, (kt + 1) & 1);

        const uint32_t base = sb + (kt & 1) * STG_BYTES;
#pragma unroll
        for (int kk = 0; kk < 4; ++kk) {
            const int ca = 2 * kk + (lmat >> 1);
            const int cb = 2 * kk + (lmat & 1);
            const int ra0 = warp_m * 32 + (lmat & 1) * 8 + lrow8;
            const int rb0 = warp_n * 32 + (lmat >> 1) * 8 + lrow8;

            uint32_t afh[2][4], afl[2][4], bfh[2][4], bfl[2][4];
            ldm_x4(afh[0], base + OFF_AH + tswz(ra0,      ca));
            ldm_x4(afh[1], base + OFF_AH + tswz(ra0 + 16, ca));
            ldm_x4(bfh[0], base + OFF_BH + tswz(rb0,      cb));
            ldm_x4(bfh[1], base + OFF_BH + tswz(rb0 + 16, cb));
            ldm_x4(bfl[0], base + OFF_BL + tswz(rb0,      cb));
            ldm_x4(bfl[1], base + OFF_BL + tswz(rb0 + 16, cb));
            // Pass 1: hi*hi — 8 independent accumulators.
#pragma unroll
            for (int mt = 0; mt < 2; ++mt)
#pragma unroll
                for (int nt = 0; nt < 4; ++nt)
                    mma16816(acc[mt][nt], afh[mt], &bfh[nt >> 1][(nt & 1) * 2]);
            ldm_x4(afl[0], base + OFF_AL + tswz(ra0,      ca));
            ldm_x4(afl[1], base + OFF_AL + tswz(ra0 + 16, ca));
            // Pass 2: hi*lo
#pragma unroll
            for (int mt = 0; mt < 2; ++mt)
#pragma unroll
                for (int nt = 0; nt < 4; ++nt)
                    mma16816(acc[mt][nt], afh[mt], &bfl[nt >> 1][(nt & 1) * 2]);
            // Pass 3: lo*hi
#pragma unroll
            for (int mt = 0; mt < 2; ++mt)
#pragma unroll
                for (int nt = 0; nt < 4; ++nt)
                    mma16816(acc[mt][nt], afl[mt], &bfh[nt >> 1][(nt & 1) * 2]);
        }
    }

    // Epilogue: add bias, store fp32 to g_xw
    const int g   = lane >> 2;
    const int tig = lane & 3;
#pragma unroll
    for (int mt = 0; mt < 2; ++mt) {
#pragma unroll
        for (int nt = 0; nt < 4; ++nt) {
            const int row = m0 + warp_m * 32 + mt * 16 + g;
            const int col = n0 + warp_n * 32 + nt * 8 + tig * 2;
            const float b0 = __ldg(bias + col);
            const float b1 = __ldg(bias + col + 1);
            float2 v0 = make_float2(acc[mt][nt][0] + b0, acc[mt][nt][1] + b1);
            float2 v1 = make_float2(acc[mt][nt][2] + b0, acc[mt][nt][3] + b1);
            *reinterpret_cast<float2*>(g_xw + (size_t)row * KDIM + col)       = v0;
            *reinterpret_cast<float2*>(g_xw + (size_t)(row + 8) * KDIM + col) = v1;
        }
    }
}

// ---------------------------------------------------------------------------
// Recurrent scan (R10/R14, best measured 125-127us): 2 chains/thread (float2),
// PF=16, HW tanh.approx for recurrence + output sigmoid, 128 x 64.
// ---------------------------------------------------------------------------
#define PF 16
__global__ __launch_bounds__(64)
void scan_kernel(const float* __restrict__ h0,
                 const float* __restrict__ dvec,
                 float* __restrict__ out,
                 int T, int BD, int D)
{
    const int p2 = blockIdx.x * blockDim.x + threadIdx.x;   // pair index
    const int idx = p2 * 2;
    if (idx >= BD) return;

    float2 dc = *reinterpret_cast<const float2*>(dvec + (idx & (D - 1)));
    dc.x = fminf(fmaxf(dc.x, -0.99f), 0.99f);
    dc.y = fminf(fmaxf(dc.y, -0.99f), 0.99f);

    float2 h = *reinterpret_cast<const float2*>(h0 + idx);
    float* __restrict__ out_h = out + (size_t)T * BD;
    __stcs(reinterpret_cast<float2*>(out_h + idx), h);

    const float* __restrict__ p = g_xw + idx;
    const size_t s = (size_t)BD;

    float2 cur[PF];
#pragma unroll
    for (int u = 0; u < PF; ++u)
        cur[u] = __ldcs(reinterpret_cast<const float2*>(p + u * s));

    for (int t0 = 0; t0 < T; t0 += PF) {
        float2 nxt[PF];
        if (t0 + PF < T) {
            const float* pn = p + (size_t)(t0 + PF) * s;
#pragma unroll
            for (int u = 0; u < PF; ++u)
                nxt[u] = __ldcs(reinterpret_cast<const float2*>(pn + u * s));
        } else {
#pragma unroll
            for (int u = 0; u < PF; ++u) nxt[u] = make_float2(0.f, 0.f);
        }
        float* __restrict__ po = out + (size_t)t0 * BD + idx;
        float* __restrict__ ph = out_h + (size_t)(t0 + 1) * BD + idx;
#pragma unroll
        for (int u = 0; u < PF; ++u) {
            const float zx = fmaf(dc.x, h.x, cur[u].x);
            const float zy = fmaf(dc.y, h.y, cur[u].y);
            asm("tanh.approx.f32 %0, %1;" : "=f"(h.x) : "f"(zx));
            asm("tanh.approx.f32 %0, %1;" : "=f"(h.y) : "f"(zy));
            float tx, ty;
            asm("tanh.approx.f32 %0, %1;" : "=f"(tx) : "f"(0.5f * h.x));
            asm("tanh.approx.f32 %0, %1;" : "=f"(ty) : "f"(0.5f * h.y));
            float2 o;
            o.x = h.x * h.x * fmaf(0.5f, tx, 0.5f);
            o.y = h.y * h.y * fmaf(0.5f, ty, 0.5f);
            __stcs(reinterpret_cast<float2*>(po + (size_t)u * BD), o);
            __stcs(reinterpret_cast<float2*>(ph + (size_t)u * BD), h);
        }
#pragma unroll
        for (int u = 0; u < PF; ++u) cur[u] = nxt[u];
    }
}

// ---------------------------------------------------------------------------
// kernel_launch: splitA + splitW -> GEMM -> scan (serial).
// ---------------------------------------------------------------------------
extern "C" void kernel_launch(void* const* d_in, const int* in_sizes, int n_in,
                              void* d_out, int out_size)
{
    (void)n_in; (void)out_size;
    const float* x  = (const float*)d_in[0];
    const float* h0 = (const float*)d_in[1];
    const float* W  = (const float*)d_in[2];
    const float* dv = (const float*)d_in[3];
    const float* b  = (const float*)d_in[4];
    float* out = (float*)d_out;

    const int D  = in_sizes[3];           // 1024
    const int BD = in_sizes[1];           // 16384
    const int T  = in_sizes[0] / BD;      // 2048
    const int M  = in_sizes[0] / D;       // 32768

    const int nA4 = (M * D) / 4;
    splitA_kernel<<<nA4 / 256, 256>>>((const float4*)x, nA4);
    const int nW4 = (D * D) / 4;
    splitW_kernel<<<(nW4 + 255) / 256, 256>>>((const float4*)W, nW4);

    cudaFuncSetAttribute(gemm_mma_kernel,
                         cudaFuncAttributeMaxDynamicSharedMemorySize, SMEM_TOTAL);
    dim3 grid(D / BN, M / BM);            // (8, 512) = 4096 CTAs, 2/SM
    gemm_mma_kernel<<<grid, 256, SMEM_TOTAL>>>(b);

    const int pairs = BD / 2;             // 8192
    scan_kernel<<<pairs / 64, 64>>>(h0, dv, out, T, BD, D);
}

// round 16
// speedup vs baseline: 1.0511x; 1.0511x over previous
#include <cuda_runtime.h>
#include <cuda_bf16.h>
#include <cstdint>
#include <math.h>

// ---------------------------------------------------------------------------
// Shapes (fixed): T=2048, B=16, D=1024.  M = T*B = 32768, K = N = 1024.
//   xw = x @ W_x^T + b  via mma.sync bf16 hi/lo split (3 MMAs), fp32 accum.
//   A and W pre-split fp32 -> bf16 hi/lo (single merged kernel, DRAM-bound);
//   GEMM stages all via cp.async.
//   scan: h_t = tanh(xw_t + d_c * h_{t-1}); out_t = h_t^2 * sigmoid(h_t)
//   d_out = [ output (T*B*D) | h ((T+1)*B*D) ]
// R16 = R14 (best, 692.9us) + merged split launch + hoisted epilogue bias.
// ---------------------------------------------------------------------------

#define KDIM 1024
#define BM 128
#define BN 256
#define BK 64                 // 64 bf16 = 128 B rows -> swizzled
#define NK (KDIM / BK)        // 16

__device__ __align__(128) float         g_xw [2048 * 16 * 1024];  // 128 MB
__device__ __align__(128) __nv_bfloat16 g_Ahi[32768 * 1024];      // 64 MB
__device__ __align__(128) __nv_bfloat16 g_Alo[32768 * 1024];      // 64 MB
__device__ __align__(128) __nv_bfloat16 g_Whi[1024 * 1024];       // 2 MB
__device__ __align__(128) __nv_bfloat16 g_Wlo[1024 * 1024];       // 2 MB

// ---------------------------------------------------------------------------
__device__ __forceinline__ void split4(float4 v, uint2& hi, uint2& lo) {
    __nv_bfloat16 hx = __float2bfloat16(v.x), hy = __float2bfloat16(v.y);
    __nv_bfloat16 hz = __float2bfloat16(v.z), hw = __float2bfloat16(v.w);
    __nv_bfloat16 lx = __float2bfloat16(v.x - __bfloat162float(hx));
    __nv_bfloat16 ly = __float2bfloat16(v.y - __bfloat162float(hy));
    __nv_bfloat16 lz = __float2bfloat16(v.z - __bfloat162float(hz));
    __nv_bfloat16 lw = __float2bfloat16(v.w - __bfloat162float(hw));
    __nv_bfloat162 h01 = __halves2bfloat162(hx, hy), h23 = __halves2bfloat162(hz, hw);
    __nv_bfloat162 l01 = __halves2bfloat162(lx, ly), l23 = __halves2bfloat162(lz, lw);
    hi.x = *reinterpret_cast<uint32_t*>(&h01); hi.y = *reinterpret_cast<uint32_t*>(&h23);
    lo.x = *reinterpret_cast<uint32_t*>(&l01); lo.y = *reinterpret_cast<uint32_t*>(&l23);
}
// Single launch: indices [0, n4a) split x -> Ahi/Alo; [n4a, n4a+n4w) split W.
__global__ void split_all_kernel(const float4* __restrict__ xa, int n4a,
                                 const float4* __restrict__ wa, int n4w) {
    int i = blockIdx.x * blockDim.x + threadIdx.x;
    if (i < n4a) {
        uint2 hi, lo; split4(xa[i], hi, lo);
        reinterpret_cast<uint2*>(g_Ahi)[i] = hi;
        reinterpret_cast<uint2*>(g_Alo)[i] = lo;
    } else if (i < n4a + n4w) {
        const int j = i - n4a;
        uint2 hi, lo; split4(wa[j], hi, lo);
        reinterpret_cast<uint2*>(g_Whi)[j] = hi;
        reinterpret_cast<uint2*>(g_Wlo)[j] = lo;
    }
}

// ---------------------------------------------------------------------------
__device__ __forceinline__ uint32_t smem_u32(const void* p) {
    uint32_t a;
    asm("{ .reg .u64 t; cvta.to.shared.u64 t, %1; cvt.u32.u64 %0, t; }" : "=r"(a) : "l"(p));
    return a;
}
__device__ __forceinline__ void cp16(uint32_t dst, const void* src) {
    asm volatile("cp.async.cg.shared.global [%0], [%1], 16;" :: "r"(dst), "l"(src));
}
#define CP_COMMIT() asm volatile("cp.async.commit_group;" ::: "memory")
#define CP_WAIT(n)  asm volatile("cp.async.wait_group %0;" :: "n"(n) : "memory")

__device__ __forceinline__ void ldm_x4(uint32_t* r, uint32_t addr) {
    asm volatile("ldmatrix.sync.aligned.m8n8.x4.shared.b16 {%0,%1,%2,%3}, [%4];"
                 : "=r"(r[0]), "=r"(r[1]), "=r"(r[2]), "=r"(r[3]) : "r"(addr));
}
__device__ __forceinline__ void mma16816(float* d, const uint32_t* a,
                                         const uint32_t* b) {
    asm volatile(
        "mma.sync.aligned.m16n8k16.row.col.f32.bf16.bf16.f32 "
        "{%0,%1,%2,%3}, {%4,%5,%6,%7}, {%8,%9}, {%0,%1,%2,%3};"
        : "+f"(d[0]), "+f"(d[1]), "+f"(d[2]), "+f"(d[3])
        : "r"(a[0]), "r"(a[1]), "r"(a[2]), "r"(a[3]), "r"(b[0]), "r"(b[1]));
}

// SMEM per stage: Ahi(16K) Alo(16K) Bhi(32K) Blo(32K) = 96 KB; 2 stages.
#define STG_BYTES   (96 * 1024)
#define OFF_AH      0
#define OFF_AL      (16 * 1024)
#define OFF_BH      (32 * 1024)
#define OFF_BL      (64 * 1024)
#define NSTG        2
#define SMEM_TOTAL  (NSTG * STG_BYTES)   // 192 KB

__device__ __forceinline__ uint32_t tswz(int row, int c) {
    return (uint32_t)(row * 128 + ((c ^ (row & 7)) * 16));
}

// ---------------------------------------------------------------------------
// GEMM (R11/R14, best measured): 512 threads, 16 warps 4(m)x4(n), warp 32x64,
// 2-stage cp.async, 3-pass reordered MMAs. Bias hoisted before the main loop.
// ---------------------------------------------------------------------------
__global__ __launch_bounds__(512, 1)
void gemm_mma_kernel(const float* __restrict__ bias) {
    extern __shared__ char smem[];
    const uint32_t sb = smem_u32(smem);
    const int tid = threadIdx.x;
    const int wid = tid >> 5;
    const int lane = tid & 31;
    const int m0 = blockIdx.y * BM;
    const int n0 = blockIdx.x * BN;

    const int warp_m = wid & 3;    // 0..3 -> 32 rows
    const int warp_n = wid >> 2;   // 0..3 -> 64 cols

    const int arow = tid >> 2;
    const int ac0  = (tid & 3) * 2;
    const int brow = tid >> 1;
    const int bc0  = (tid & 1) * 4;

    auto stage_in = [&](int kt, int stg) {
        const uint32_t base = sb + stg * STG_BYTES;
        const size_t ga = (size_t)(m0 + arow) * KDIM + kt * BK;
        const size_t gb = (size_t)(n0 + brow) * KDIM + kt * BK;
#pragma unroll
        for (int j = 0; j < 2; ++j) {
            const int c = ac0 + j;
            const uint32_t so = tswz(arow, c);
            cp16(base + OFF_AH + so, g_Ahi + ga + c * 8);
            cp16(base + OFF_AL + so, g_Alo + ga + c * 8);
        }
#pragma unroll
        for (int j = 0; j < 4; ++j) {
            const int c = bc0 + j;
            const uint32_t so = tswz(brow, c);
            cp16(base + OFF_BH + so, g_Whi + gb + c * 8);
            cp16(base + OFF_BL + so, g_Wlo + gb + c * 8);
        }
        CP_COMMIT();
    };

    float acc[2][8][4];
#pragma unroll
    for (int i = 0; i < 2; ++i)
#pragma unroll
        for (int j = 0; j < 8; ++j)
#pragma unroll
            for (int q = 0; q < 4; ++q) acc[i][j][q] = 0.0f;

    stage_in(0, 0);

    // Hoist epilogue bias: 16 values per thread (2 per nt, nt = 0..7).
    const int tig = lane & 3;
    float bb[8][2];
#pragma unroll
    for (int nt = 0; nt < 8; ++nt) {
        const int col = n0 + warp_n * 64 + nt * 8 + tig * 2;
        bb[nt][0] = __ldg(bias + col);
        bb[nt][1] = __ldg(bias + col + 1);
    }

    const int lmat  = lane >> 3;
    const int lrow8 = lane & 7;

    for (int kt = 0; kt < NK; ++kt) {
        CP_WAIT(0);
        __syncthreads();

        if (kt + 1 < NK) stage_in(kt + 1, (kt + 1) & 1);

        const uint32_t base = sb + (kt & 1) * STG_BYTES;
#pragma unroll
        for (int kk = 0; kk < 4; ++kk) {
            const int ca = 2 * kk + (lmat >> 1);
            const int cb = 2 * kk + (lmat & 1);
            const int ra0 = warp_m * 32 + (lmat & 1) * 8 + lrow8;

            uint32_t afh[2][4], afl[2][4];
            ldm_x4(afh[0], base + OFF_AH + tswz(ra0,      ca));
            ldm_x4(afh[1], base + OFF_AH + tswz(ra0 + 16, ca));
            ldm_x4(afl[0], base + OFF_AL + tswz(ra0,      ca));
            ldm_x4(afl[1], base + OFF_AL + tswz(ra0 + 16, ca));

#pragma unroll
            for (int c2 = 0; c2 < 2; ++c2) {
                const int rb0 = warp_n * 64 + c2 * 32 + (lmat >> 1) * 8 + lrow8;
                uint32_t bfh[2][4], bfl[2][4];
                ldm_x4(bfh[0], base + OFF_BH + tswz(rb0,      cb));
                ldm_x4(bfh[1], base + OFF_BH + tswz(rb0 + 16, cb));
                ldm_x4(bfl[0], base + OFF_BL + tswz(rb0,      cb));
                ldm_x4(bfl[1], base + OFF_BL + tswz(rb0 + 16, cb));
#pragma unroll
                for (int mt = 0; mt < 2; ++mt)
#pragma unroll
                    for (int nt = 0; nt < 4; ++nt)
                        mma16816(acc[mt][c2 * 4 + nt], afh[mt], &bfh[nt >> 1][(nt & 1) * 2]);
#pragma unroll
                for (int mt = 0; mt < 2; ++mt)
#pragma unroll
                    for (int nt = 0; nt < 4; ++nt)
                        mma16816(acc[mt][c2 * 4 + nt], afh[mt], &bfl[nt >> 1][(nt & 1) * 2]);
#pragma unroll
                for (int mt = 0; mt < 2; ++mt)
#pragma unroll
                    for (int nt = 0; nt < 4; ++nt)
                        mma16816(acc[mt][c2 * 4 + nt], afl[mt], &bfh[nt >> 1][(nt & 1) * 2]);
            }
        }
    }

    // Epilogue: add (hoisted) bias, store fp32 to g_xw.
    const int g = lane >> 2;
#pragma unroll
    for (int mt = 0; mt < 2; ++mt) {
#pragma unroll
        for (int nt = 0; nt < 8; ++nt) {
            const int row = m0 + warp_m * 32 + mt * 16 + g;
            const int col = n0 + warp_n * 64 + nt * 8 + tig * 2;
            float2 v0 = make_float2(acc[mt][nt][0] + bb[nt][0], acc[mt][nt][1] + bb[nt][1]);
            float2 v1 = make_float2(acc[mt][nt][2] + bb[nt][0], acc[mt][nt][3] + bb[nt][1]);
            *reinterpret_cast<float2*>(g_xw + (size_t)row * KDIM + col)       = v0;
            *reinterpret_cast<float2*>(g_xw + (size_t)(row + 8) * KDIM + col) = v1;
        }
    }
}

// ---------------------------------------------------------------------------
// Recurrent scan (R10/R14, best measured 125-127us): 2 chains/thread (float2),
// PF=16, HW tanh.approx for recurrence + output sigmoid, 128 x 64.
// ---------------------------------------------------------------------------
#define PF 16
__global__ __launch_bounds__(64)
void scan_kernel(const float* __restrict__ h0,
                 const float* __restrict__ dvec,
                 float* __restrict__ out,
                 int T, int BD, int D)
{
    const int p2 = blockIdx.x * blockDim.x + threadIdx.x;   // pair index
    const int idx = p2 * 2;
    if (idx >= BD) return;

    float2 dc = *reinterpret_cast<const float2*>(dvec + (idx & (D - 1)));
    dc.x = fminf(fmaxf(dc.x, -0.99f), 0.99f);
    dc.y = fminf(fmaxf(dc.y, -0.99f), 0.99f);

    float2 h = *reinterpret_cast<const float2*>(h0 + idx);
    float* __restrict__ out_h = out + (size_t)T * BD;
    __stcs(reinterpret_cast<float2*>(out_h + idx), h);

    const float* __restrict__ p = g_xw + idx;
    const size_t s = (size_t)BD;

    float2 cur[PF];
#pragma unroll
    for (int u = 0; u < PF; ++u)
        cur[u] = __ldcs(reinterpret_cast<const float2*>(p + u * s));

    for (int t0 = 0; t0 < T; t0 += PF) {
        float2 nxt[PF];
        if (t0 + PF < T) {
            const float* pn = p + (size_t)(t0 + PF) * s;
#pragma unroll
            for (int u = 0; u < PF; ++u)
                nxt[u] = __ldcs(reinterpret_cast<const float2*>(pn + u * s));
        } else {
#pragma unroll
            for (int u = 0; u < PF; ++u) nxt[u] = make_float2(0.f, 0.f);
        }
        float* __restrict__ po = out + (size_t)t0 * BD + idx;
        float* __restrict__ ph = out_h + (size_t)(t0 + 1) * BD + idx;
#pragma unroll
        for (int u = 0; u < PF; ++u) {
            const float zx = fmaf(dc.x, h.x, cur[u].x);
            const float zy = fmaf(dc.y, h.y, cur[u].y);
            asm("tanh.approx.f32 %0, %1;" : "=f"(h.x) : "f"(zx));
            asm("tanh.approx.f32 %0, %1;" : "=f"(h.y) : "f"(zy));
            float tx, ty;
            asm("tanh.approx.f32 %0, %1;" : "=f"(tx) : "f"(0.5f * h.x));
            asm("tanh.approx.f32 %0, %1;" : "=f"(ty) : "f"(0.5f * h.y));
            float2 o;
            o.x = h.x * h.x * fmaf(0.5f, tx, 0.5f);
            o.y = h.y * h.y * fmaf(0.5f, ty, 0.5f);
            __stcs(reinterpret_cast<float2*>(po + (size_t)u * BD), o);
            __stcs(reinterpret_cast<float2*>(ph + (size_t)u * BD), h);
        }
#pragma unroll
        for (int u = 0; u < PF; ++u) cur[u] = nxt[u];
    }
}

// ---------------------------------------------------------------------------
// kernel_launch: merged split -> GEMM -> scan (serial).
// ---------------------------------------------------------------------------
extern "C" void kernel_launch(void* const* d_in, const int* in_sizes, int n_in,
                              void* d_out, int out_size)
{
    (void)n_in; (void)out_size;
    const float* x  = (const float*)d_in[0];
    const float* h0 = (const float*)d_in[1];
    const float* W  = (const float*)d_in[2];
    const float* dv = (const float*)d_in[3];
    const float* b  = (const float*)d_in[4];
    float* out = (float*)d_out;

    const int D  = in_sizes[3];           // 1024
    const int BD = in_sizes[1];           // 16384
    const int T  = in_sizes[0] / BD;      // 2048
    const int M  = in_sizes[0] / D;       // 32768

    const int nA4 = (M * D) / 4;          // 8,388,608
    const int nW4 = (D * D) / 4;          // 262,144
    split_all_kernel<<<(nA4 + nW4 + 255) / 256, 256>>>(
        (const float4*)x, nA4, (const float4*)W, nW4);

    cudaFuncSetAttribute(gemm_mma_kernel,
                         cudaFuncAttributeMaxDynamicSharedMemorySize, SMEM_TOTAL);
    dim3 grid(D / BN, M / BM);            // (4, 256)
    gemm_mma_kernel<<<grid, 512, SMEM_TOTAL>>>(b);

    const int pairs = BD / 2;             // 8192
    scan_kernel<<<pairs / 64, 64>>>(h0, dv, out, T, BD, D);
}

// round 17
// speedup vs baseline: 1.0585x; 1.0070x over previous
#include <cuda_runtime.h>
#include <cuda_bf16.h>
#include <cstdint>
#include <math.h>

// ---------------------------------------------------------------------------
// Shapes (fixed): T=2048, B=16, D=1024.  M = T*B = 32768, K = N = 1024.
//   xw = x @ W_x^T + b  via mma.sync bf16 hi/lo split (3 MMAs), fp32 accum.
//   A and W pre-split fp32 -> bf16 hi/lo (single merged kernel, DRAM-bound);
//   GEMM stages all via cp.async.
//   scan: h_t = tanh(xw_t + d_c * h_{t-1}); out_t = h_t^2 * sigmoid(h_t)
//   d_out = [ output (T*B*D) | h ((T+1)*B*D) ]
// R17 = R16 + PERSISTENT GEMM: nsm CTAs loop over the 1024 tiles with the
// cp.async pipeline kept warm across tiles (prologue paid once per CTA;
// epilogue of tile t overlaps the staging of tile t+1).
// ---------------------------------------------------------------------------

#define KDIM 1024
#define BM 128
#define BN 256
#define BK 64                 // 64 bf16 = 128 B rows -> swizzled
#define NK (KDIM / BK)        // 16
#define NTILE_N (KDIM / BN)   // 4
#define NTILES  ((32768 / BM) * NTILE_N)   // 1024

__device__ __align__(128) float         g_xw [2048 * 16 * 1024];  // 128 MB
__device__ __align__(128) __nv_bfloat16 g_Ahi[32768 * 1024];      // 64 MB
__device__ __align__(128) __nv_bfloat16 g_Alo[32768 * 1024];      // 64 MB
__device__ __align__(128) __nv_bfloat16 g_Whi[1024 * 1024];       // 2 MB
__device__ __align__(128) __nv_bfloat16 g_Wlo[1024 * 1024];       // 2 MB

// ---------------------------------------------------------------------------
__device__ __forceinline__ void split4(float4 v, uint2& hi, uint2& lo) {
    __nv_bfloat16 hx = __float2bfloat16(v.x), hy = __float2bfloat16(v.y);
    __nv_bfloat16 hz = __float2bfloat16(v.z), hw = __float2bfloat16(v.w);
    __nv_bfloat16 lx = __float2bfloat16(v.x - __bfloat162float(hx));
    __nv_bfloat16 ly = __float2bfloat16(v.y - __bfloat162float(hy));
    __nv_bfloat16 lz = __float2bfloat16(v.z - __bfloat162float(hz));
    __nv_bfloat16 lw = __float2bfloat16(v.w - __bfloat162float(hw));
    __nv_bfloat162 h01 = __halves2bfloat162(hx, hy), h23 = __halves2bfloat162(hz, hw);
    __nv_bfloat162 l01 = __halves2bfloat162(lx, ly), l23 = __halves2bfloat162(lz, lw);
    hi.x = *reinterpret_cast<uint32_t*>(&h01); hi.y = *reinterpret_cast<uint32_t*>(&h23);
    lo.x = *reinterpret_cast<uint32_t*>(&l01); lo.y = *reinterpret_cast<uint32_t*>(&l23);
}
__global__ void split_all_kernel(const float4* __restrict__ xa, int n4a,
                                 const float4* __restrict__ wa, int n4w) {
    int i = blockIdx.x * blockDim.x + threadIdx.x;
    if (i < n4a) {
        uint2 hi, lo; split4(xa[i], hi, lo);
        reinterpret_cast<uint2*>(g_Ahi)[i] = hi;
        reinterpret_cast<uint2*>(g_Alo)[i] = lo;
    } else if (i < n4a + n4w) {
        const int j = i - n4a;
        uint2 hi, lo; split4(wa[j], hi, lo);
        reinterpret_cast<uint2*>(g_Whi)[j] = hi;
        reinterpret_cast<uint2*>(g_Wlo)[j] = lo;
    }
}

// ---------------------------------------------------------------------------
__device__ __forceinline__ uint32_t smem_u32(const void* p) {
    uint32_t a;
    asm("{ .reg .u64 t; cvta.to.shared.u64 t, %1; cvt.u32.u64 %0, t; }" : "=r"(a) : "l"(p));
    return a;
}
__device__ __forceinline__ void cp16(uint32_t dst, const void* src) {
    asm volatile("cp.async.cg.shared.global [%0], [%1], 16;" :: "r"(dst), "l"(src));
}
#define CP_COMMIT() asm volatile("cp.async.commit_group;" ::: "memory")
#define CP_WAIT(n)  asm volatile("cp.async.wait_group %0;" :: "n"(n) : "memory")

__device__ __forceinline__ void ldm_x4(uint32_t* r, uint32_t addr) {
    asm volatile("ldmatrix.sync.aligned.m8n8.x4.shared.b16 {%0,%1,%2,%3}, [%4];"
                 : "=r"(r[0]), "=r"(r[1]), "=r"(r[2]), "=r"(r[3]) : "r"(addr));
}
__device__ __forceinline__ void mma16816(float* d, const uint32_t* a,
                                         const uint32_t* b) {
    asm volatile(
        "mma.sync.aligned.m16n8k16.row.col.f32.bf16.bf16.f32 "
        "{%0,%1,%2,%3}, {%4,%5,%6,%7}, {%8,%9}, {%0,%1,%2,%3};"
        : "+f"(d[0]), "+f"(d[1]), "+f"(d[2]), "+f"(d[3])
        : "r"(a[0]), "r"(a[1]), "r"(a[2]), "r"(a[3]), "r"(b[0]), "r"(b[1]));
}

// SMEM per stage: Ahi(16K) Alo(16K) Bhi(32K) Blo(32K) = 96 KB; 2 stages.
#define STG_BYTES   (96 * 1024)
#define OFF_AH      0
#define OFF_AL      (16 * 1024)
#define OFF_BH      (32 * 1024)
#define OFF_BL      (64 * 1024)
#define SMEM_TOTAL  (2 * STG_BYTES)   // 192 KB

__device__ __forceinline__ uint32_t tswz(int row, int c) {
    return (uint32_t)(row * 128 + ((c ^ (row & 7)) * 16));
}

// ---------------------------------------------------------------------------
// Persistent GEMM: g_xw[m,n] = sum_k A[m,k]*W[n,k] + bias[n]
// nsm CTAs; each loops tiles (tile += gridDim.x). 512 threads, 16 warps
// (4m x 4n, warp 32x64), 2-stage cp.async kept warm ACROSS tiles.
// ---------------------------------------------------------------------------
__global__ __launch_bounds__(512, 1)
void gemm_mma_kernel(const float* __restrict__ bias) {
    extern __shared__ char smem[];
    const uint32_t sb = smem_u32(smem);
    const int tid = threadIdx.x;
    const int wid = tid >> 5;
    const int lane = tid & 31;

    const int warp_m = wid & 3;    // 0..3 -> 32 rows
    const int warp_n = wid >> 2;   // 0..3 -> 64 cols

    const int arow = tid >> 2;
    const int ac0  = (tid & 3) * 2;
    const int brow = tid >> 1;
    const int bc0  = (tid & 1) * 4;

    // tile -> (m0, n0): n-major within tile index so consecutive CTAs share A rows.
    auto tile_m0 = [&](int t) { return (t >> 2) * BM; };
    auto tile_n0 = [&](int t) { return (t & 3) * BN; };

    auto stage_in = [&](int m0, int n0, int kt, int stg) {
        const uint32_t base = sb + stg * STG_BYTES;
        const size_t ga = (size_t)(m0 + arow) * KDIM + kt * BK;
        const size_t gb = (size_t)(n0 + brow) * KDIM + kt * BK;
#pragma unroll
        for (int j = 0; j < 2; ++j) {
            const int c = ac0 + j;
            const uint32_t so = tswz(arow, c);
            cp16(base + OFF_AH + so, g_Ahi + ga + c * 8);
            cp16(base + OFF_AL + so, g_Alo + ga + c * 8);
        }
#pragma unroll
        for (int j = 0; j < 4; ++j) {
            const int c = bc0 + j;
            const uint32_t so = tswz(brow, c);
            cp16(base + OFF_BH + so, g_Whi + gb + c * 8);
            cp16(base + OFF_BL + so, g_Wlo + gb + c * 8);
        }
        CP_COMMIT();
    };

    const int lmat  = lane >> 3;
    const int lrow8 = lane & 7;
    const int tig   = lane & 3;
    const int g     = lane >> 2;

    // Prologue: stage first tile's ktile 0.
    stage_in(tile_m0(blockIdx.x), tile_n0(blockIdx.x), 0, 0);
    int stg = 0;

    for (int tile = blockIdx.x; tile < NTILES; tile += gridDim.x) {
        const int m0 = tile_m0(tile);
        const int n0 = tile_n0(tile);
        const int ntile = tile + gridDim.x;

        // Hoist epilogue bias for this tile.
        float bb[8][2];
#pragma unroll
        for (int nt = 0; nt < 8; ++nt) {
            const int col = n0 + warp_n * 64 + nt * 8 + tig * 2;
            bb[nt][0] = __ldg(bias + col);
            bb[nt][1] = __ldg(bias + col + 1);
        }

        float acc[2][8][4];
#pragma unroll
        for (int i = 0; i < 2; ++i)
#pragma unroll
            for (int j = 0; j < 8; ++j)
#pragma unroll
                for (int q = 0; q < 4; ++q) acc[i][j][q] = 0.0f;

        for (int kt = 0; kt < NK; ++kt) {
            CP_WAIT(0);
            __syncthreads();

            // Stage next ktile, or the NEXT TILE's ktile 0 (pipe stays warm).
            if (kt + 1 < NK)           stage_in(m0, n0, kt + 1, stg ^ 1);
            else if (ntile < NTILES)   stage_in(tile_m0(ntile), tile_n0(ntile), 0, stg ^ 1);

            const uint32_t base = sb + stg * STG_BYTES;
#pragma unroll
            for (int kk = 0; kk < 4; ++kk) {
                const int ca = 2 * kk + (lmat >> 1);
                const int cb = 2 * kk + (lmat & 1);
                const int ra0 = warp_m * 32 + (lmat & 1) * 8 + lrow8;

                uint32_t afh[2][4], afl[2][4];
                ldm_x4(afh[0], base + OFF_AH + tswz(ra0,      ca));
                ldm_x4(afh[1], base + OFF_AH + tswz(ra0 + 16, ca));
                ldm_x4(afl[0], base + OFF_AL + tswz(ra0,      ca));
                ldm_x4(afl[1], base + OFF_AL + tswz(ra0 + 16, ca));

#pragma unroll
                for (int c2 = 0; c2 < 2; ++c2) {
                    const int rb0 = warp_n * 64 + c2 * 32 + (lmat >> 1) * 8 + lrow8;
                    uint32_t bfh[2][4], bfl[2][4];
                    ldm_x4(bfh[0], base + OFF_BH + tswz(rb0,      cb));
                    ldm_x4(bfh[1], base + OFF_BH + tswz(rb0 + 16, cb));
                    ldm_x4(bfl[0], base + OFF_BL + tswz(rb0,      cb));
                    ldm_x4(bfl[1], base + OFF_BL + tswz(rb0 + 16, cb));
#pragma unroll
                    for (int mt = 0; mt < 2; ++mt)
#pragma unroll
                        for (int nt = 0; nt < 4; ++nt)
                            mma16816(acc[mt][c2 * 4 + nt], afh[mt], &bfh[nt >> 1][(nt & 1) * 2]);
#pragma unroll
                    for (int mt = 0; mt < 2; ++mt)
#pragma unroll
                        for (int nt = 0; nt < 4; ++nt)
                            mma16816(acc[mt][c2 * 4 + nt], afh[mt], &bfl[nt >> 1][(nt & 1) * 2]);
#pragma unroll
                    for (int mt = 0; mt < 2; ++mt)
#pragma unroll
                        for (int nt = 0; nt < 4; ++nt)
                            mma16816(acc[mt][c2 * 4 + nt], afl[mt], &bfh[nt >> 1][(nt & 1) * 2]);
                }
            }
            stg ^= 1;
        }

        // Epilogue (no smem): overlaps the in-flight cp.async of next tile.
#pragma unroll
        for (int mt = 0; mt < 2; ++mt) {
#pragma unroll
            for (int nt = 0; nt < 8; ++nt) {
                const int row = m0 + warp_m * 32 + mt * 16 + g;
                const int col = n0 + warp_n * 64 + nt * 8 + tig * 2;
                float2 v0 = make_float2(acc[mt][nt][0] + bb[nt][0], acc[mt][nt][1] + bb[nt][1]);
                float2 v1 = make_float2(acc[mt][nt][2] + bb[nt][0], acc[mt][nt][3] + bb[nt][1]);
                *reinterpret_cast<float2*>(g_xw + (size_t)row * KDIM + col)       = v0;
                *reinterpret_cast<float2*>(g_xw + (size_t)(row + 8) * KDIM + col) = v1;
            }
        }
    }
}

// ---------------------------------------------------------------------------
// Recurrent scan (R10/R14, best measured 125-127us): 2 chains/thread (float2),
// PF=16, HW tanh.approx for recurrence + output sigmoid, 128 x 64.
// ---------------------------------------------------------------------------
#define PF 16
__global__ __launch_bounds__(64)
void scan_kernel(const float* __restrict__ h0,
                 const float* __restrict__ dvec,
                 float* __restrict__ out,
                 int T, int BD, int D)
{
    const int p2 = blockIdx.x * blockDim.x + threadIdx.x;   // pair index
    const int idx = p2 * 2;
    if (idx >= BD) return;

    float2 dc = *reinterpret_cast<const float2*>(dvec + (idx & (D - 1)));
    dc.x = fminf(fmaxf(dc.x, -0.99f), 0.99f);
    dc.y = fminf(fmaxf(dc.y, -0.99f), 0.99f);

    float2 h = *reinterpret_cast<const float2*>(h0 + idx);
    float* __restrict__ out_h = out + (size_t)T * BD;
    __stcs(reinterpret_cast<float2*>(out_h + idx), h);

    const float* __restrict__ p = g_xw + idx;
    const size_t s = (size_t)BD;

    float2 cur[PF];
#pragma unroll
    for (int u = 0; u < PF; ++u)
        cur[u] = __ldcs(reinterpret_cast<const float2*>(p + u * s));

    for (int t0 = 0; t0 < T; t0 += PF) {
        float2 nxt[PF];
        if (t0 + PF < T) {
            const float* pn = p + (size_t)(t0 + PF) * s;
#pragma unroll
            for (int u = 0; u < PF; ++u)
                nxt[u] = __ldcs(reinterpret_cast<const float2*>(pn + u * s));
        } else {
#pragma unroll
            for (int u = 0; u < PF; ++u) nxt[u] = make_float2(0.f, 0.f);
        }
        float* __restrict__ po = out + (size_t)t0 * BD + idx;
        float* __restrict__ ph = out_h + (size_t)(t0 + 1) * BD + idx;
#pragma unroll
        for (int u = 0; u < PF; ++u) {
            const float zx = fmaf(dc.x, h.x, cur[u].x);
            const float zy = fmaf(dc.y, h.y, cur[u].y);
            asm("tanh.approx.f32 %0, %1;" : "=f"(h.x) : "f"(zx));
            asm("tanh.approx.f32 %0, %1;" : "=f"(h.y) : "f"(zy));
            float tx, ty;
            asm("tanh.approx.f32 %0, %1;" : "=f"(tx) : "f"(0.5f * h.x));
            asm("tanh.approx.f32 %0, %1;" : "=f"(ty) : "f"(0.5f * h.y));
            float2 o;
            o.x = h.x * h.x * fmaf(0.5f, tx, 0.5f);
            o.y = h.y * h.y * fmaf(0.5f, ty, 0.5f);
            __stcs(reinterpret_cast<float2*>(po + (size_t)u * BD), o);
            __stcs(reinterpret_cast<float2*>(ph + (size_t)u * BD), h);
        }
#pragma unroll
        for (int u = 0; u < PF; ++u) cur[u] = nxt[u];
    }
}

// ---------------------------------------------------------------------------
// kernel_launch: merged split -> persistent GEMM -> scan (serial).
// ---------------------------------------------------------------------------
extern "C" void kernel_launch(void* const* d_in, const int* in_sizes, int n_in,
                              void* d_out, int out_size)
{
    (void)n_in; (void)out_size;
    const float* x  = (const float*)d_in[0];
    const float* h0 = (const float*)d_in[1];
    const float* W  = (const float*)d_in[2];
    const float* dv = (const float*)d_in[3];
    const float* b  = (const float*)d_in[4];
    float* out = (float*)d_out;

    const int D  = in_sizes[3];           // 1024
    const int BD = in_sizes[1];           // 16384
    const int T  = in_sizes[0] / BD;      // 2048
    const int M  = in_sizes[0] / D;       // 32768

    static int nsm = 0;
    if (nsm == 0) {
        cudaDeviceGetAttribute(&nsm, cudaDevAttrMultiProcessorCount, 0);
        if (nsm <= 0) nsm = 148;
        cudaFuncSetAttribute(gemm_mma_kernel,
                             cudaFuncAttributeMaxDynamicSharedMemorySize, SMEM_TOTAL);
    }

    const int nA4 = (M * D) / 4;          // 8,388,608
    const int nW4 = (D * D) / 4;          // 262,144
    split_all_kernel<<<(nA4 + nW4 + 255) / 256, 256>>>(
        (const float4*)x, nA4, (const float4*)W, nW4);

    gemm_mma_kernel<<<nsm, 512, SMEM_TOTAL>>>(b);

    const int pairs = BD / 2;             // 8192
    scan_kernel<<<pairs / 64, 64>>>(h0, dv, out, T, BD, D);
}